// round 17
// baseline (speedup 1.0000x reference)
#include <cuda_runtime.h>
#include <math.h>

#define HID  128
#define BINS 513
#define WIN  1024
#define ENCN 256

// ---------------- device scratch (kernel boundaries order all access) ----------------
__device__ __align__(16) float g_h1[HID], g_h2[HID], g_h1b[HID], g_h2b[HID];
__device__ __align__(16) float g_sr[BINS+3], g_si[BINS+3];
__device__ __align__(16) float g_encP[32*ENCN];
__device__ __align__(16) float g_enc[ENCN];

__device__ __forceinline__ float sigm(float x){ return 1.0f/(1.0f+__expf(-x)); }

__device__ __forceinline__ float wsum(float v){
#pragma unroll
    for (int o = 16; o > 0; o >>= 1) v += __shfl_xor_sync(0xffffffffu, v, o);
    return v;
}
__device__ __forceinline__ void wsum2(float& a, float& b){
#pragma unroll
    for (int o = 16; o > 0; o >>= 1){
        a += __shfl_xor_sync(0xffffffffu, a, o);
        b += __shfl_xor_sync(0xffffffffu, b, o);
    }
}
__device__ __forceinline__ void wsum4(float& a, float& b, float& c, float& d){
#pragma unroll
    for (int o = 16; o > 0; o >>= 1){
        a += __shfl_xor_sync(0xffffffffu, a, o);
        b += __shfl_xor_sync(0xffffffffu, b, o);
        c += __shfl_xor_sync(0xffffffffu, c, o);
        d += __shfl_xor_sync(0xffffffffu, d, o);
    }
}

// ================= K1: LSTM1 layer0 (16 CTAs) =================
__global__ void __launch_bounds__(256) k1_lstm1a(
    const float* __restrict__ mag, const float* __restrict__ st1,
    const float* __restrict__ wih10, const float* __restrict__ whh10,
    const float* __restrict__ bih10, const float* __restrict__ bhh10,
    float* __restrict__ out)
{
    const int lane = threadIdx.x & 31, wid = threadIdx.x >> 5;
    const int j = blockIdx.x * 8 + wid;           // 0..127
    float wiA[4][17], whA[4][4], bA[4], xrA[17], hrA[4];
#pragma unroll
    for (int g = 0; g < 4; g++){
        const float* w = wih10 + (size_t)(g*HID + j)*BINS;
#pragma unroll
        for (int i = 0; i < 17; i++){ int k = lane + 32*i; wiA[g][i] = (k < BINS) ? w[k] : 0.f; }
        const float* wh = whh10 + (size_t)(g*HID + j)*HID;
#pragma unroll
        for (int i = 0; i < 4; i++) whA[g][i] = wh[lane + 32*i];
        bA[g] = bih10[g*HID + j] + bhh10[g*HID + j];
    }
#pragma unroll
    for (int i = 0; i < 17; i++){ int k = lane + 32*i; xrA[i] = (k < BINS) ? mag[k] : 0.f; }
#pragma unroll
    for (int i = 0; i < 4; i++) hrA[i] = st1[lane + 32*i];
    float cprev = st1[2*HID + j];

    float a0=0.f,a1=0.f,a2=0.f,a3=0.f;
#pragma unroll
    for (int i = 0; i < 17; i++){
        float x = xrA[i];
        a0 = fmaf(wiA[0][i], x, a0); a1 = fmaf(wiA[1][i], x, a1);
        a2 = fmaf(wiA[2][i], x, a2); a3 = fmaf(wiA[3][i], x, a3);
    }
#pragma unroll
    for (int i = 0; i < 4; i++){
        float h = hrA[i];
        a0 = fmaf(whA[0][i], h, a0); a1 = fmaf(whA[1][i], h, a1);
        a2 = fmaf(whA[2][i], h, a2); a3 = fmaf(whA[3][i], h, a3);
    }
    wsum4(a0,a1,a2,a3);
    if (lane == 0){
        float c2 = sigm(a1+bA[1])*cprev + sigm(a0+bA[0])*tanhf(a2+bA[2]);
        float h2 = sigm(a3+bA[3])*tanhf(c2);
        out[WIN + j] = h2; out[WIN + 2*HID + j] = c2;
        g_h1[j] = h2;
    }
}

// ================= generic small LSTM (128-in) kernel body =================
__device__ __forceinline__ void lstm128(
    int j, int lane, const float* xsrc, const float* hprev, float cprev,
    const float* wih, const float* whh, const float* bih, const float* bhh,
    float* hout_g, float* hout_o, float* cout_o)
{
    float4 wi[4], wh[4]; float b[4];
#pragma unroll
    for (int g = 0; g < 4; g++){
        wi[g] = *(const float4*)(wih + (size_t)(g*HID + j)*HID + lane*4);
        wh[g] = *(const float4*)(whh + (size_t)(g*HID + j)*HID + lane*4);
        b[g]  = bih[g*HID + j] + bhh[g*HID + j];
    }
    float4 hr = *(const float4*)(hprev + lane*4);
    float4 x  = *(const float4*)(xsrc + lane*4);
    float a0 = wi[0].x*x.x+wi[0].y*x.y+wi[0].z*x.z+wi[0].w*x.w + wh[0].x*hr.x+wh[0].y*hr.y+wh[0].z*hr.z+wh[0].w*hr.w;
    float a1 = wi[1].x*x.x+wi[1].y*x.y+wi[1].z*x.z+wi[1].w*x.w + wh[1].x*hr.x+wh[1].y*hr.y+wh[1].z*hr.z+wh[1].w*hr.w;
    float a2 = wi[2].x*x.x+wi[2].y*x.y+wi[2].z*x.z+wi[2].w*x.w + wh[2].x*hr.x+wh[2].y*hr.y+wh[2].z*hr.z+wh[2].w*hr.w;
    float a3 = wi[3].x*x.x+wi[3].y*x.y+wi[3].z*x.z+wi[3].w*x.w + wh[3].x*hr.x+wh[3].y*hr.y+wh[3].z*hr.z+wh[3].w*hr.w;
    wsum4(a0,a1,a2,a3);
    if (lane == 0){
        float c2 = sigm(a1+b[1])*cprev + sigm(a0+b[0])*tanhf(a2+b[2]);
        float h2 = sigm(a3+b[3])*tanhf(c2);
        *hout_g = h2; *hout_o = h2; *cout_o = c2;
    }
}

// ================= K2: LSTM1 layer1 (16 CTAs) =================
__global__ void __launch_bounds__(256) k2_lstm1b(
    const float* __restrict__ st1,
    const float* __restrict__ wih11, const float* __restrict__ whh11,
    const float* __restrict__ bih11, const float* __restrict__ bhh11,
    float* __restrict__ out)
{
    const int lane = threadIdx.x & 31, wid = threadIdx.x >> 5;
    const int j = blockIdx.x * 8 + wid;
    lstm128(j, lane, g_h1, st1 + HID, st1[3*HID + j],
            wih11, whh11, bih11, bhh11,
            &g_h2[j], &out[WIN + HID + j], &out[WIN + 3*HID + j]);
}

// ================= K3: dense1 -> spectrum (32 CTAs) =================
__global__ void __launch_bounds__(256) k3_dense1(
    const float* __restrict__ mag, const float* __restrict__ phase,
    const float* __restrict__ d1w, const float* __restrict__ d1b)
{
    const int lane = threadIdx.x & 31, wid = threadIdx.x >> 5;
    const int ew = blockIdx.x * 8 + wid;          // 0..255
    int r0 = 2*ew;
    float4 wD0 = *(const float4*)(d1w + (size_t)(r0+0)*HID + lane*4);
    float4 wD1 = *(const float4*)(d1w + (size_t)(r0+1)*HID + lane*4);
    float b0 = d1b[r0+0], b1 = d1b[r0+1];
    float m0 = mag[r0+0], m1 = mag[r0+1];
    float c0,s0,c1,s1;
    sincosf(phase[r0+0], &s0, &c0);  sincosf(phase[r0+1], &s1, &c1);
    float4 w512 = make_float4(0.f,0.f,0.f,0.f);
    float b5=0.f, m5=0.f, c5=1.f, s5=0.f;
    if (ew == 0){
        w512 = *(const float4*)(d1w + (size_t)512*HID + lane*4);
        b5 = d1b[512]; m5 = mag[512];
        sincosf(phase[512], &s5, &c5);
    }
    float4 x = *(const float4*)&g_h2[lane*4];
    float a0 = wD0.x*x.x+wD0.y*x.y+wD0.z*x.z+wD0.w*x.w;
    float a1 = wD1.x*x.x+wD1.y*x.y+wD1.z*x.z+wD1.w*x.w;
    wsum2(a0, a1);
    if (lane == 0){
        float e0 = sigm(a0+b0)*m0, e1 = sigm(a1+b1)*m1;
        g_sr[r0]   = e0*c0;  g_si[r0]   = e0*s0;
        g_sr[r0+1] = e1*c1;  g_si[r0+1] = e1*s1;
    }
    if (ew == 0){
        float a5 = w512.x*x.x+w512.y*x.y+w512.z*x.z+w512.w*x.w;
        a5 = wsum(a5);
        if (lane == 0){
            float e5 = sigm(a5+b5)*m5;
            g_sr[512] = e5*c5;  g_si[512] = e5*s5;
        }
    }
}

// ================= K4: iDFT + partial encoder (32 CTAs) =================
__global__ void __launch_bounds__(256) k4_idft_encp(const float* __restrict__ encw)
{
    __shared__ float encwT[32*257];
    __shared__ float y1s[32];
    const int tid = threadIdx.x, lane = tid & 31, wid = tid >> 5;
    const int cta = blockIdx.x;                  // 0..31
    const int fw = cta * 8 + wid;                // 0..255
    const int n_base = cta * 32;
    for (int i = tid; i < 256*32; i += 256){
        int e = i >> 5, nl = i & 31;
        encwT[nl*257 + e] = encw[(size_t)e*WIN + n_base + nl];
    }

    int n0 = fw*4;
    float cc[4], ss[4], cd[4], sd[4], acc[4];
#pragma unroll
    for (int q = 0; q < 4; q++){
        int n = n0 + q;
        int m0i = ((1+lane)*n) & (WIN-1);
        int mdi = (32*n) & (WIN-1);
        float sA, cA, sD, cD;
        sincospif((float)m0i * (1.0f/512.0f), &sA, &cA);
        sincospif((float)mdi * (1.0f/512.0f), &sD, &cD);
        cc[q] = cA; ss[q] = sA; cd[q] = cD; sd[q] = sD;
        acc[q] = 0.f;
    }
    float dc  = g_sr[0];
    float nyq = g_sr[512];
    float srv[16], siv[16];
#pragma unroll
    for (int t = 0; t < 16; t++){
        int k = 1 + lane + 32*t;
        srv[t] = (k < 512) ? g_sr[k] : 0.f;
        siv[t] = (k < 512) ? g_si[k] : 0.f;
    }
#pragma unroll
    for (int t = 0; t < 16; t++){
        float sr_ = srv[t], si_ = siv[t];
#pragma unroll
        for (int q = 0; q < 4; q++){
            acc[q] = fmaf(sr_, cc[q], acc[q]);
            acc[q] = fmaf(-si_, ss[q], acc[q]);
            float cn = cc[q]*cd[q] - ss[q]*sd[q];
            ss[q]    = ss[q]*cd[q] + cc[q]*sd[q];
            cc[q]    = cn;
        }
    }
    wsum4(acc[0],acc[1],acc[2],acc[3]);
    if (lane == 0){
#pragma unroll
        for (int q = 0; q < 4; q++){
            int n = n0 + q;
            float ny = (n & 1) ? -nyq : nyq;
            y1s[wid*4 + q] = (dc + 2.0f*acc[q] + ny) * (1.0f/1024.0f);
        }
    }
    __syncthreads();
    float acc2 = 0.f;
#pragma unroll
    for (int nl = 0; nl < 32; nl++)
        acc2 = fmaf(encwT[nl*257 + tid], y1s[nl], acc2);
    g_encP[cta*ENCN + tid] = acc2;
}

// ================= K5: sum partials + norm + LSTM2a (16 CTAs) =================
__global__ void __launch_bounds__(256) k5_norm_lstm2a(
    const float* __restrict__ st2,
    const float* __restrict__ gamma_, const float* __restrict__ beta_,
    const float* __restrict__ wih20, const float* __restrict__ whh20,
    const float* __restrict__ bih20, const float* __restrict__ bhh20,
    float* __restrict__ out)
{
    __shared__ float red[8], red2[8], encn[ENCN];
    const int tid = threadIdx.x, lane = tid & 31, wid = tid >> 5;
    const int j = blockIdx.x * 8 + wid;
    float4 wi0[4], wi1[4], wh[4]; float b[4];
#pragma unroll
    for (int g = 0; g < 4; g++){
        wi0[g] = *(const float4*)(wih20 + (size_t)(g*HID + j)*ENCN + lane*8);
        wi1[g] = *(const float4*)(wih20 + (size_t)(g*HID + j)*ENCN + lane*8 + 4);
        wh[g]  = *(const float4*)(whh20 + (size_t)(g*HID + j)*HID + lane*4);
        b[g]   = bih20[g*HID + j] + bhh20[g*HID + j];
    }
    float4 hr = *(const float4*)(st2 + lane*4);
    float cprev = st2[2*HID + j];
    float gamv = gamma_[tid], betv = beta_[tid];

    float v = 0.f;
#pragma unroll
    for (int s = 0; s < 32; s++) v += g_encP[s*ENCN + tid];
    if (blockIdx.x == 0) g_enc[tid] = v;

    float sv = v, sq = v*v;
    wsum2(sv, sq);
    if (lane == 0){ red[wid] = sv; red2[wid] = sq; }
    __syncthreads();
    float tot = 0.f, tot2 = 0.f;
#pragma unroll
    for (int i = 0; i < 8; i++){ tot += red[i]; tot2 += red2[i]; }
    float mean = tot * (1.0f/ENCN);
    float var  = tot2 * (1.0f/ENCN) - mean*mean;
    float rstd = rsqrtf(var + 1e-7f);
    encn[tid] = (v - mean) * rstd * gamv + betv;
    __syncthreads();

    float4 x0 = *(const float4*)&encn[lane*8];
    float4 x1 = *(const float4*)&encn[lane*8 + 4];
    float a0 = wi0[0].x*x0.x+wi0[0].y*x0.y+wi0[0].z*x0.z+wi0[0].w*x0.w + wi1[0].x*x1.x+wi1[0].y*x1.y+wi1[0].z*x1.z+wi1[0].w*x1.w
             + wh[0].x*hr.x+wh[0].y*hr.y+wh[0].z*hr.z+wh[0].w*hr.w;
    float a1 = wi0[1].x*x0.x+wi0[1].y*x0.y+wi0[1].z*x0.z+wi0[1].w*x0.w + wi1[1].x*x1.x+wi1[1].y*x1.y+wi1[1].z*x1.z+wi1[1].w*x1.w
             + wh[1].x*hr.x+wh[1].y*hr.y+wh[1].z*hr.z+wh[1].w*hr.w;
    float a2 = wi0[2].x*x0.x+wi0[2].y*x0.y+wi0[2].z*x0.z+wi0[2].w*x0.w + wi1[2].x*x1.x+wi1[2].y*x1.y+wi1[2].z*x1.z+wi1[2].w*x1.w
             + wh[2].x*hr.x+wh[2].y*hr.y+wh[2].z*hr.z+wh[2].w*hr.w;
    float a3 = wi0[3].x*x0.x+wi0[3].y*x0.y+wi0[3].z*x0.z+wi0[3].w*x0.w + wi1[3].x*x1.x+wi1[3].y*x1.y+wi1[3].z*x1.z+wi1[3].w*x1.w
             + wh[3].x*hr.x+wh[3].y*hr.y+wh[3].z*hr.z+wh[3].w*hr.w;
    wsum4(a0,a1,a2,a3);
    if (lane == 0){
        float c2 = sigm(a1+b[1])*cprev + sigm(a0+b[0])*tanhf(a2+b[2]);
        float h2 = sigm(a3+b[3])*tanhf(c2);
        out[WIN + 4*HID + j] = h2; out[WIN + 6*HID + j] = c2;
        g_h1b[j] = h2;
    }
}

// ================= K6: LSTM2 layer1 (16 CTAs) =================
__global__ void __launch_bounds__(256) k6_lstm2b(
    const float* __restrict__ st2,
    const float* __restrict__ wih21, const float* __restrict__ whh21,
    const float* __restrict__ bih21, const float* __restrict__ bhh21,
    float* __restrict__ out)
{
    const int lane = threadIdx.x & 31, wid = threadIdx.x >> 5;
    const int j = blockIdx.x * 8 + wid;
    lstm128(j, lane, g_h1b, st2 + HID, st2[3*HID + j],
            wih21, whh21, bih21, bhh21,
            &g_h2b[j], &out[WIN + 5*HID + j], &out[WIN + 7*HID + j]);
}

// ================= K7: dense2 + est + decoder (32 CTAs) =================
__global__ void __launch_bounds__(256) k7_est_dec(
    const float* __restrict__ d2w, const float* __restrict__ d2b,
    const float* __restrict__ decw, float* __restrict__ out)
{
    __shared__ float h2bS[HID];
    __shared__ float estS[ENCN];
    const int tid = threadIdx.x, lane = tid & 31, wid = tid >> 5;
    const int fw = blockIdx.x * 8 + wid;          // 0..255
    if (tid < HID) h2bS[tid] = g_h2b[tid];
    float encv = g_enc[tid];
    float d2bv = d2b[tid];
    __syncthreads();
    {
        const float4* h2b4 = (const float4*)h2bS;
        const float4* wr = (const float4*)(d2w + (size_t)tid*HID);
        float acc = 0.f;
#pragma unroll
        for (int k4 = 0; k4 < 32; k4++){
            float4 w = wr[k4];
            float4 h = h2b4[k4];
            acc += w.x*h.x + w.y*h.y + w.z*h.z + w.w*h.w;
        }
        estS[tid] = sigm(acc + d2bv) * encv;
    }
    __syncthreads();
    {
        const float4* est4 = (const float4*)estS;
        float4 e0 = est4[lane*2], e1 = est4[lane*2 + 1];
        int n0 = fw*4;
        float a0=0.f,a1=0.f,a2=0.f,a3=0.f;
#pragma unroll
        for (int q = 0; q < 4; q++){
            const float* wr = decw + (size_t)(n0+q)*ENCN;
            float4 w0 = *(const float4*)(wr + lane*8);
            float4 w1 = *(const float4*)(wr + lane*8 + 4);
            float acc = w0.x*e0.x + w0.y*e0.y + w0.z*e0.z + w0.w*e0.w
                      + w1.x*e1.x + w1.y*e1.y + w1.z*e1.z + w1.w*e1.w;
            if (q==0) a0 = acc; else if (q==1) a1 = acc; else if (q==2) a2 = acc; else a3 = acc;
        }
        wsum4(a0,a1,a2,a3);
        if (lane == 0){
            out[n0+0] = a0; out[n0+1] = a1; out[n0+2] = a2; out[n0+3] = a3;
        }
    }
}

extern "C" void kernel_launch(void* const* d_in, const int* in_sizes, int n_in,
                              void* d_out, int out_size)
{
    (void)in_sizes; (void)n_in; (void)out_size;
    const float* mag    = (const float*)d_in[0];
    const float* phase  = (const float*)d_in[1];
    const float* st1    = (const float*)d_in[2];
    const float* st2    = (const float*)d_in[3];
    const float* wih10  = (const float*)d_in[4];
    const float* whh10  = (const float*)d_in[5];
    const float* bih10  = (const float*)d_in[6];
    const float* bhh10  = (const float*)d_in[7];
    const float* wih11  = (const float*)d_in[8];
    const float* whh11  = (const float*)d_in[9];
    const float* bih11  = (const float*)d_in[10];
    const float* bhh11  = (const float*)d_in[11];
    const float* d1w    = (const float*)d_in[12];
    const float* d1b    = (const float*)d_in[13];
    const float* encw   = (const float*)d_in[14];
    const float* gamma_ = (const float*)d_in[15];
    const float* beta_  = (const float*)d_in[16];
    const float* wih20  = (const float*)d_in[17];
    const float* whh20  = (const float*)d_in[18];
    const float* bih20  = (const float*)d_in[19];
    const float* bhh20  = (const float*)d_in[20];
    const float* wih21  = (const float*)d_in[21];
    const float* whh21  = (const float*)d_in[22];
    const float* bih21  = (const float*)d_in[23];
    const float* bhh21  = (const float*)d_in[24];
    const float* d2w    = (const float*)d_in[25];
    const float* d2b    = (const float*)d_in[26];
    const float* decw   = (const float*)d_in[27];
    float* out = (float*)d_out;

    k1_lstm1a   <<<16, 256>>>(mag, st1, wih10, whh10, bih10, bhh10, out);
    k2_lstm1b   <<<16, 256>>>(st1, wih11, whh11, bih11, bhh11, out);
    k3_dense1   <<<32, 256>>>(mag, phase, d1w, d1b);
    k4_idft_encp<<<32, 256>>>(encw);
    k5_norm_lstm2a<<<16, 256>>>(st2, gamma_, beta_, wih20, whh20, bih20, bhh20, out);
    k6_lstm2b   <<<16, 256>>>(st2, wih21, whh21, bih21, bhh21, out);
    k7_est_dec  <<<32, 256>>>(d2w, d2b, decw, out);
}